// round 1
// baseline (speedup 1.0000x reference)
#include <cuda_runtime.h>
#include <cuda_bf16.h>

#define BATCH 16384
#define DIM   1024
#define NL    4
#define DIM4  (DIM / 4)

// Scratch (no allocation allowed): row-independent constants.
__device__ float g_D[NL];       // D_l = dot(c_l, W_l),  c_l = sum_{j<l} b_j
__device__ float g_Csum[DIM];   // Csum = b0+b1+b2+b3

// ---------------------------------------------------------------------------
// Precompute kernel: 1 CTA, 1024 threads. Reads 32 KB, writes 4+1024 floats.
// ---------------------------------------------------------------------------
__global__ __launch_bounds__(DIM) void crossnet_precompute(
    const float* __restrict__ W, const float* __restrict__ b)
{
    int d = threadIdx.x;
    float b0 = b[0 * DIM + d];
    float b1 = b[1 * DIM + d];
    float b2 = b[2 * DIM + d];
    float b3 = b[3 * DIM + d];

    float c1 = b0;
    float c2 = c1 + b1;
    float c3 = c2 + b2;
    g_Csum[d] = c3 + b3;

    float p1 = c1 * W[1 * DIM + d];
    float p2 = c2 * W[2 * DIM + d];
    float p3 = c3 * W[3 * DIM + d];

    // warp reduce
    #pragma unroll
    for (int o = 16; o; o >>= 1) {
        p1 += __shfl_xor_sync(0xFFFFFFFFu, p1, o);
        p2 += __shfl_xor_sync(0xFFFFFFFFu, p2, o);
        p3 += __shfl_xor_sync(0xFFFFFFFFu, p3, o);
    }

    __shared__ float sm[3][32];
    int warp = threadIdx.x >> 5;
    int lane = threadIdx.x & 31;
    if (lane == 0) { sm[0][warp] = p1; sm[1][warp] = p2; sm[2][warp] = p3; }
    __syncthreads();

    if (warp == 0) {
        float q1 = sm[0][lane];
        float q2 = sm[1][lane];
        float q3 = sm[2][lane];
        #pragma unroll
        for (int o = 16; o; o >>= 1) {
            q1 += __shfl_xor_sync(0xFFFFFFFFu, q1, o);
            q2 += __shfl_xor_sync(0xFFFFFFFFu, q2, o);
            q3 += __shfl_xor_sync(0xFFFFFFFFu, q3, o);
        }
        if (lane == 0) {
            g_D[0] = 0.0f;
            g_D[1] = q1;
            g_D[2] = q2;
            g_D[3] = q3;
        }
    }
}

// ---------------------------------------------------------------------------
// Main kernel: one warp per row. 8 float4 of x0 per lane stay in registers.
// out = a4(row) * x0 + Csum.   Zero __syncthreads in the hot path.
// ---------------------------------------------------------------------------
__global__ __launch_bounds__(256) void crossnet_main(
    const float4* __restrict__ x0,
    const float4* __restrict__ W4,
    float4* __restrict__ out)
{
    int warp = threadIdx.x >> 5;
    int lane = threadIdx.x & 31;
    int row  = blockIdx.x * 8 + warp;

    const float4* xr = x0 + (size_t)row * DIM4;

    float4 xv[8];
    float u0 = 0.f, u1 = 0.f, u2 = 0.f, u3 = 0.f;

    #pragma unroll
    for (int k = 0; k < 8; k++) {
        int i = k * 32 + lane;
        float4 x = xr[i];
        xv[k] = x;
        float4 w0 = W4[0 * DIM4 + i];
        float4 w1 = W4[1 * DIM4 + i];
        float4 w2 = W4[2 * DIM4 + i];
        float4 w3 = W4[3 * DIM4 + i];
        u0 = fmaf(x.x, w0.x, fmaf(x.y, w0.y, fmaf(x.z, w0.z, fmaf(x.w, w0.w, u0))));
        u1 = fmaf(x.x, w1.x, fmaf(x.y, w1.y, fmaf(x.z, w1.z, fmaf(x.w, w1.w, u1))));
        u2 = fmaf(x.x, w2.x, fmaf(x.y, w2.y, fmaf(x.z, w2.z, fmaf(x.w, w2.w, u2))));
        u3 = fmaf(x.x, w3.x, fmaf(x.y, w3.y, fmaf(x.z, w3.z, fmaf(x.w, w3.w, u3))));
    }

    // warp reduce the 4 dot products (independent chains, pipeline nicely)
    #pragma unroll
    for (int o = 16; o; o >>= 1) {
        u0 += __shfl_xor_sync(0xFFFFFFFFu, u0, o);
        u1 += __shfl_xor_sync(0xFFFFFFFFu, u1, o);
        u2 += __shfl_xor_sync(0xFFFFFFFFu, u2, o);
        u3 += __shfl_xor_sync(0xFFFFFFFFu, u3, o);
    }

    // scalar recurrence: a_{l+1} = a_l + (a_l * u_l + D_l)
    float a = 1.0f;
    a += fmaf(a, u0, g_D[0]);
    a += fmaf(a, u1, g_D[1]);
    a += fmaf(a, u2, g_D[2]);
    a += fmaf(a, u3, g_D[3]);

    const float4* C = (const float4*)g_Csum;
    float4* outr = out + (size_t)row * DIM4;

    #pragma unroll
    for (int k = 0; k < 8; k++) {
        int i = k * 32 + lane;
        float4 c = C[i];
        float4 x = xv[k];
        float4 o4;
        o4.x = fmaf(a, x.x, c.x);
        o4.y = fmaf(a, x.y, c.y);
        o4.z = fmaf(a, x.z, c.z);
        o4.w = fmaf(a, x.w, c.w);
        outr[i] = o4;
    }
}

extern "C" void kernel_launch(void* const* d_in, const int* in_sizes, int n_in,
                              void* d_out, int out_size)
{
    const float* x0 = (const float*)d_in[0];   // [16384, 1024]
    const float* W  = (const float*)d_in[1];   // [4, 1024]
    const float* b  = (const float*)d_in[2];   // [4, 1024]
    float* out      = (float*)d_out;           // [16384, 1024]

    crossnet_precompute<<<1, DIM>>>(W, b);
    crossnet_main<<<BATCH / 8, 256>>>((const float4*)x0, (const float4*)W,
                                      (float4*)out);
}